// round 15
// baseline (speedup 1.0000x reference)
#include <cuda_runtime.h>
#include <cuda_fp16.h>

#define BB  4
#define CC  256
#define CQK 32
#define NN  4096
#define LOG2E 1.4426950408889634f

// q/k: fp16 [b][n][c], word-pair-permuted per k16 chunk (8 words):
//   stored order [w0,w4,w1,w5,w2,w6,w3,w7] (word = 2 adjacent c).
//   q pre-scaled by log2(e).
// v: fp16 [b][c][m], same word-perm per 8-word (16-m) group.
__device__ __half g_qt[BB * NN * CQK];
__device__ __half g_kt[BB * NN * CQK];
__device__ __half g_v [(size_t)BB * CC * NN];

// ---- flash smem layout (32-bit word slots) — 64-row blocks
#define OFF_Q  0            // 64 x 24 (16 words/row + pad)
#define OFF_K  1536         // 2 x 64 x 24
#define OFF_V  4608         // 2 x 256 x 40
#define SMEM_FLOATS 25088   // 100352 B; epilogue fT 256x68 fp32 reuses OFF_K..

// ---- proj smem layout (floats)
#define P_OFF_SX 0          // 2 x 128 x 36
#define P_OFF_SW 9216       // 2 x 320 x 36
#define P_OFF_SB 32256      // 320
#define P_SMEM_FLOATS 32576 // 130304 bytes (epilogue 80x132 reuses P_OFF_SW)

// ===========================================================================
__device__ __forceinline__ unsigned smem_u32(const void* p) {
    unsigned a;
    asm("{ .reg .u64 t; cvta.to.shared.u64 t, %1; cvt.u32.u64 %0, t; }"
        : "=r"(a) : "l"(p));
    return a;
}
__device__ __forceinline__ float ex2(float x) {
    float y;
    asm("ex2.approx.ftz.f32 %0, %1;" : "=f"(y) : "f"(x));
    return y;
}
// pack two fp32 -> f16x2 word (lo = first element)
__device__ __forceinline__ unsigned packh(float lo, float hi) {
    unsigned r;
    asm("cvt.rn.f16x2.f32 %0, %1, %2;" : "=r"(r) : "f"(hi), "f"(lo));
    return r;
}
__device__ __forceinline__ void cp16(unsigned dst, const void* src) {
    asm volatile("cp.async.cg.shared.global [%0], [%1], 16;" :: "r"(dst), "l"(src));
}
__device__ __forceinline__ void cp4(unsigned dst, const void* src) {
    asm volatile("cp.async.ca.shared.global [%0], [%1], 4;" :: "r"(dst), "l"(src));
}
#define CP_COMMIT()  asm volatile("cp.async.commit_group;")
#define CP_WAIT(n)   asm volatile("cp.async.wait_group %0;" :: "n"(n))

__device__ __forceinline__ void lds2(unsigned addr, unsigned& x, unsigned& y) {
    asm volatile("ld.shared.v2.b32 {%0, %1}, [%2];" : "=r"(x), "=r"(y) : "r"(addr));
}
__device__ __forceinline__ unsigned lds1(unsigned addr) {
    unsigned v;
    asm volatile("ld.shared.b32 %0, [%1];" : "=r"(v) : "r"(addr));
    return v;
}
__device__ __forceinline__ void mma8(float c[4],
                                     unsigned a0, unsigned a1, unsigned a2, unsigned a3,
                                     unsigned b0, unsigned b1) {
    asm volatile(
        "mma.sync.aligned.m16n8k8.row.col.f32.tf32.tf32.f32 "
        "{%0,%1,%2,%3}, {%4,%5,%6,%7}, {%8,%9}, {%0,%1,%2,%3};"
        : "+f"(c[0]), "+f"(c[1]), "+f"(c[2]), "+f"(c[3])
        : "r"(a0), "r"(a1), "r"(a2), "r"(a3), "r"(b0), "r"(b1));
}
__device__ __forceinline__ void mma16h(float c[4],
                                       unsigned a0, unsigned a1, unsigned a2, unsigned a3,
                                       unsigned b0, unsigned b1) {
    asm volatile(
        "mma.sync.aligned.m16n8k16.row.col.f32.f16.f16.f32 "
        "{%0,%1,%2,%3}, {%4,%5,%6,%7}, {%8,%9}, {%0,%1,%2,%3};"
        : "+f"(c[0]), "+f"(c[1]), "+f"(c[2]), "+f"(c[3])
        : "r"(a0), "r"(a1), "r"(a2), "r"(a3), "r"(b0), "r"(b1));
}

// ===========================================================================
// 1) Fused q+k+v projection via tensor cores (tf32 GEMM);
//    epilogue packs q/k/v to fp16 with word-perm; LOG2E folded into q.
// ===========================================================================
__global__ __launch_bounds__(256, 1) void proj_fused_kernel(
        const float* __restrict__ x,
        const float* __restrict__ Wq, const float* __restrict__ bq,
        const float* __restrict__ Wk, const float* __restrict__ bk,
        const float* __restrict__ Wv, const float* __restrict__ bv) {
    extern __shared__ float psm[];

    const int b   = blockIdx.y;
    const int n0  = blockIdx.x * 128;
    const int tid = threadIdx.x;
    const int wid = tid >> 5, lane = tid & 31;
    const int r4 = lane >> 2, q = lane & 3;
    const int wm = wid >> 1, wn = wid & 1;

    const unsigned sb4 = smem_u32(psm);
    const unsigned sX  = sb4 + P_OFF_SX * 4;
    const unsigned sW  = sb4 + P_OFF_SW * 4;
    float* fB = psm + P_OFF_SB;

    {
        int i = tid;
        if (i < 32) fB[i] = bq[i];
        else if (i < 64) fB[i] = bk[i - 32];
        else fB[i] = bv[i - 64];
        i = tid + 256;
        if (i < 320) fB[i] = bv[i - 64];
    }

    auto issue = [&](int ch) {
        const int buf = ch & 1;
        const unsigned wd = sW + (unsigned)buf * (320 * 36 * 4);
#pragma unroll
        for (int i = 0; i < 10; i++) {
            int idx = tid + i * 256;
            int row = idx >> 3, seg = idx & 7;
            int c = ch * 32 + seg * 4;
            const float* src = (row < 32) ? (Wq + row * 256 + c)
                             : (row < 64) ? (Wk + (row - 32) * 256 + c)
                                          : (Wv + (row - 64) * 256 + c);
            cp16(wd + (unsigned)(row * 36 + seg * 4) * 4, src);
        }
        const unsigned xd = sX + (unsigned)buf * (128 * 36 * 4);
#pragma unroll
        for (int i = 0; i < 16; i++) {
            int idx = tid + i * 256;
            int c = idx >> 7, n = idx & 127;
            cp4(xd + (unsigned)(n * 36 + c) * 4,
                x + ((size_t)b * CC + ch * 32 + c) * NN + n0 + n);
        }
        CP_COMMIT();
    };

    float acc[5][8][4];
#pragma unroll
    for (int mt = 0; mt < 5; mt++)
#pragma unroll
        for (int nt = 0; nt < 8; nt++)
#pragma unroll
            for (int j = 0; j < 4; j++) acc[mt][nt][j] = 0.f;

    issue(0);
    for (int ch = 0; ch < 8; ch++) {
        if (ch < 7) { issue(ch + 1); CP_WAIT(1); }
        else        { CP_WAIT(0); }
        __syncthreads();

        const int buf = ch & 1;
        const unsigned swb = sW + (unsigned)buf * (320 * 36 * 4);
        const unsigned sxb = sX + (unsigned)buf * (128 * 36 * 4);
#pragma unroll
        for (int kk = 0; kk < 4; kk++) {
            unsigned a[5][4];
#pragma unroll
            for (int mt = 0; mt < 5; mt++) {
                unsigned base = swb + (unsigned)((wm * 80 + mt * 16 + r4) * 36 + kk * 8 + q) * 4;
                a[mt][0] = lds1(base);
                a[mt][1] = lds1(base + 8 * 36 * 4);
                a[mt][2] = lds1(base + 16);
                a[mt][3] = lds1(base + 8 * 36 * 4 + 16);
            }
            unsigned bb[8][2];
#pragma unroll
            for (int nt = 0; nt < 8; nt++) {
                unsigned nb = sxb + (unsigned)((wn * 64 + nt * 8 + r4) * 36 + kk * 8 + q) * 4;
                bb[nt][0] = lds1(nb);
                bb[nt][1] = lds1(nb + 16);
            }
#pragma unroll
            for (int mt = 0; mt < 5; mt++)
#pragma unroll
                for (int nt = 0; nt < 8; nt++)
                    mma8(acc[mt][nt], a[mt][0], a[mt][1], a[mt][2], a[mt][3],
                         bb[nt][0], bb[nt][1]);
        }
        __syncthreads();
    }

    float* fE = psm + P_OFF_SW;   // 80 x 132
#pragma unroll 1
    for (int ocg = 0; ocg < 4; ocg++) {
        __syncthreads();
        if (wm == ocg) {
#pragma unroll
            for (int mt = 0; mt < 5; mt++)
#pragma unroll
                for (int nt = 0; nt < 8; nt++)
#pragma unroll
                    for (int j = 0; j < 4; j++) {
                        int row = mt * 16 + r4 + 8 * (j >> 1);
                        int col = wn * 64 + nt * 8 + 2 * q + (j & 1);
                        fE[row * 132 + col] = acc[mt][nt][j] + fB[ocg * 80 + row];
                    }
        }
        __syncthreads();

        if (ocg == 0) {
            // rows 0..31: q, rows 32..63: k -> fp16 [n][c-wordperm];
            // rows 64..79: v c=0..15 fp16
#pragma unroll
            for (int i = 0; i < 2; i++) {
                int item = tid + i * 256;
                if (item < 256) {
                    int n = item & 127, half = item >> 7;
                    const float sc = half ? 1.0f : LOG2E;
                    float vv[32];
#pragma unroll
                    for (int o = 0; o < 32; o++)
                        vv[o] = fE[(half * 32 + o) * 132 + n] * sc;
                    unsigned w[16];
#pragma unroll
                    for (int j = 0; j < 16; j++) w[j] = packh(vv[2*j], vv[2*j+1]);
                    __half* hdst = (half ? g_kt : g_qt) + ((size_t)b * NN + n0 + n) * CQK;
                    uint4* d = (uint4*)hdst;
                    d[0] = make_uint4(w[0],  w[4],  w[1],  w[5]);
                    d[1] = make_uint4(w[2],  w[6],  w[3],  w[7]);
                    d[2] = make_uint4(w[8],  w[12], w[9],  w[13]);
                    d[3] = make_uint4(w[10], w[14], w[11], w[15]);
                } else {
                    int it = item - 256;
                    if (it < 128) {
                        int row = 64 + (it >> 3), gt = it & 7;
                        int c = row - 64;
                        const float* f = fE + row * 132 + gt * 16;
                        unsigned w[8];
#pragma unroll
                        for (int p = 0; p < 8; p++) w[p] = packh(f[2*p], f[2*p+1]);
                        uint4* d = (uint4*)(g_v + ((size_t)b * CC + c) * NN + n0 + gt * 16);
                        d[0] = make_uint4(w[0], w[4], w[1], w[5]);
                        d[1] = make_uint4(w[2], w[6], w[3], w[7]);
                    }
                }
            }
        } else {
#pragma unroll
            for (int i = 0; i < 3; i++) {
                int item = tid + i * 256;
                if (item < 640) {
                    int row = item >> 3, gt = item & 7;
                    int c = ocg * 80 + row - 64;
                    const float* f = fE + row * 132 + gt * 16;
                    unsigned w[8];
#pragma unroll
                    for (int p = 0; p < 8; p++) w[p] = packh(f[2*p], f[2*p+1]);
                    uint4* d = (uint4*)(g_v + ((size_t)b * CC + c) * NN + n0 + gt * 16);
                    d[0] = make_uint4(w[0], w[4], w[1], w[5]);
                    d[1] = make_uint4(w[2], w[6], w[3], w[7]);
                }
            }
        }
    }
}

// ===========================================================================
// 2) Flash attention, 64-row blocks, 2 CTAs/SM, fp16 k16 mma, warp tile
//    16n x 128c. INTRA-STEP PIPELINE: after the max-reduce, the g-loop fuses
//    {ex2, l-accum, pack af[g], 16 PV mmas} so softmax ALU of chunk g+1
//    overlaps chunk g's mma/lds stream. One __syncthreads per step.
// ===========================================================================
__global__ __launch_bounds__(256, 2) void flash_kernel(const float* __restrict__ x,
                                                       float* __restrict__ out) {
    extern __shared__ float sm[];

    const int b   = blockIdx.y;
    const int n0  = blockIdx.x * 64;
    const int tid = threadIdx.x;
    const int wid = tid >> 5, lane = tid & 31;
    const int r4 = lane >> 2, q = lane & 3;
    const int wr = wid >> 1, wc = wid & 1;

    const unsigned sb  = smem_u32(sm);
    const unsigned sQ  = sb + OFF_Q * 4;
    const unsigned sK  = sb + OFF_K * 4;
    const unsigned sV  = sb + OFF_V * 4;

    const __half* qg  = g_qt + ((size_t)b * NN + n0) * CQK;
    const __half* kg0 = g_kt + (size_t)b * NN * CQK;
    const __half* vg0 = g_v  + (size_t)b * CC * NN;

    // ---- prologue: q tile (64x32 fp16) + first K/V tiles via cp.async
    cp16(sQ + (unsigned)((tid >> 2) * 24 + (tid & 3) * 4) * 4,
         qg + (size_t)(tid >> 2) * CQK + (tid & 3) * 8);
    cp16(sK + (unsigned)((tid >> 2) * 24 + (tid & 3) * 4) * 4,
         kg0 + (size_t)(tid >> 2) * CQK + (tid & 3) * 8);
#pragma unroll
    for (int i = 0; i < 8; i++) {      // V: 256 c-rows x 32 words
        int idx = tid + i * 256;
        int row = idx >> 3, p = idx & 7;
        cp16(sV + (unsigned)(row * 40 + p * 4) * 4,
             vg0 + (size_t)row * NN + p * 8);
    }
    CP_COMMIT();
    CP_WAIT(0);
    __syncthreads();

    // q fragments: warp owns rows 16*wr..+15 (LOG2E pre-folded)
    const int rowS = 16 * wr + r4;
    unsigned qf[2][4];
#pragma unroll
    for (int kk = 0; kk < 2; kk++) {
        lds2(sQ + (unsigned)(rowS * 24 + kk * 8 + 2 * q) * 4,
             qf[kk][0], qf[kk][2]);
        lds2(sQ + (unsigned)((rowS + 8) * 24 + kk * 8 + 2 * q) * 4,
             qf[kk][1], qf[kk][3]);
    }

    // out accumulator: 16 rows x 128 c -> 16 nt fragments
    float acc[16][4];
#pragma unroll
    for (int nt = 0; nt < 16; nt++)
#pragma unroll
        for (int j = 0; j < 4; j++) acc[nt][j] = 0.f;

    float mA = -1e30f, mB = -1e30f, lA = 0.f, lB = 0.f;

    const int STEPS = NN / 64;
    for (int s = 0; s < STEPS; s++) {
        if (s > 0) CP_WAIT(1);   // K(s) ready (V(s) may still be in flight)
        __syncthreads();         // all warps done with buf(s^1) reads

        if (s + 1 < STEPS) {
            const int m1 = (s + 1) * 64;
            // K(s+1): its own commit group
            const unsigned kd = sK + (unsigned)((s + 1) & 1) * (64 * 24 * 4);
            cp16(kd + (unsigned)((tid >> 2) * 24 + (tid & 3) * 4) * 4,
                 kg0 + (size_t)(m1 + (tid >> 2)) * CQK + (tid & 3) * 8);
            CP_COMMIT();
            // V(s+1): separate commit group
            const unsigned vd = sV + (unsigned)((s + 1) & 1) * (256 * 40 * 4);
#pragma unroll
            for (int i = 0; i < 8; i++) {
                int idx = tid + i * 256;
                int row = idx >> 3, p = idx & 7;
                cp16(vd + (unsigned)(row * 40 + p * 4) * 4,
                     vg0 + (size_t)row * NN + m1 + p * 8);
            }
            CP_COMMIT();
        }

        // ---- scores (fp16 k16): own 16 rows x 64 m (duplicated across c-pair)
        const unsigned kbuf = sK + (unsigned)(s & 1) * (64 * 24 * 4);
        float sacc[8][4];
#pragma unroll
        for (int nt = 0; nt < 8; nt++)
#pragma unroll
            for (int j = 0; j < 4; j++) sacc[nt][j] = 0.f;

#pragma unroll
        for (int kk = 0; kk < 2; kk++) {
#pragma unroll
            for (int nt = 0; nt < 8; nt++) {
                unsigned b0, b1;
                lds2(kbuf + (unsigned)((nt * 8 + r4) * 24 + kk * 8 + 2 * q) * 4,
                     b0, b1);
                mma16h(sacc[nt], qf[kk][0], qf[kk][1], qf[kk][2], qf[kk][3],
                       b0, b1);
            }
        }

        // ---- max reduce (the only full-tile dependency)
        float rmA = sacc[0][0], rmB = sacc[0][2];
#pragma unroll
        for (int nt = 0; nt < 8; nt++) {
            rmA = fmaxf(rmA, fmaxf(sacc[nt][0], sacc[nt][1]));
            rmB = fmaxf(rmB, fmaxf(sacc[nt][2], sacc[nt][3]));
        }
#pragma unroll
        for (int off = 1; off <= 2; off <<= 1) {
            rmA = fmaxf(rmA, __shfl_xor_sync(0xffffffffu, rmA, off));
            rmB = fmaxf(rmB, __shfl_xor_sync(0xffffffffu, rmB, off));
        }
        const float mnA = fmaxf(mA, rmA), mnB = fmaxf(mB, rmB);
        const float scA = ex2(mA - mnA),  scB = ex2(mB - mnB);
        mA = mnA; mB = mnB;

        // ---- rescale acc (warp-local, skip when maxes unchanged)
        if (!__all_sync(0xffffffffu, (scA == 1.f) && (scB == 1.f))) {
#pragma unroll
            for (int nt = 0; nt < 16; nt++) {
                acc[nt][0] *= scA; acc[nt][1] *= scA;
                acc[nt][2] *= scB; acc[nt][3] *= scB;
            }
        }

        // ---- V(s) must be resident before PV reads it
        if (s + 1 < STEPS) { CP_WAIT(2); }   // pending: V(s),K(s+1),V(s+1)
        else               { CP_WAIT(0); }   // last step: drain everything

        // ---- fused softmax + PV: per chunk g {ex2, l-accum, pack, 16 mmas}
        const unsigned vbuf = sV + (unsigned)(s & 1) * (256 * 40 * 4);
        float lsA = 0.f, lsB = 0.f;
#pragma unroll
        for (int g = 0; g < 4; g++) {
            float p0 = ex2(sacc[2*g][0]   - mnA);
            float p1 = ex2(sacc[2*g][1]   - mnA);
            float p2 = ex2(sacc[2*g][2]   - mnB);
            float p3 = ex2(sacc[2*g][3]   - mnB);
            float p4 = ex2(sacc[2*g+1][0] - mnA);
            float p5 = ex2(sacc[2*g+1][1] - mnA);
            float p6 = ex2(sacc[2*g+1][2] - mnB);
            float p7 = ex2(sacc[2*g+1][3] - mnB);
            lsA += (p0 + p1) + (p4 + p5);
            lsB += (p2 + p3) + (p6 + p7);
            unsigned a0 = packh(p0, p1);
            unsigned a1 = packh(p2, p3);
            unsigned a2 = packh(p4, p5);
            unsigned a3 = packh(p6, p7);
#pragma unroll
            for (int nt = 0; nt < 16; nt++) {
                unsigned b0, b1;
                lds2(vbuf + (unsigned)((wc * 128 + nt * 8 + r4) * 40 + g * 8 + 2 * q) * 4,
                     b0, b1);
                mma16h(acc[nt], a0, a1, a2, a3, b0, b1);
            }
        }
#pragma unroll
        for (int off = 1; off <= 2; off <<= 1) {
            lsA += __shfl_xor_sync(0xffffffffu, lsA, off);
            lsB += __shfl_xor_sync(0xffffffffu, lsB, off);
        }
        lA = lA * scA + lsA;
        lB = lB * scB + lsB;
    }

    // ---- normalize by l (warp-local)
    const float linvA = 1.f / lA, linvB = 1.f / lB;
#pragma unroll
    for (int nt = 0; nt < 16; nt++) {
        acc[nt][0] *= linvA; acc[nt][1] *= linvA;
        acc[nt][2] *= linvB; acc[nt][3] *= linvB;
    }

    // ---- epilogue: transpose 64n x 256c -> [c][n] via smem (reuse K+V), +x
    float* fT = sm + OFF_K;   // 256 x 68
    __syncthreads();
#pragma unroll
    for (int nt = 0; nt < 16; nt++)
#pragma unroll
        for (int j = 0; j < 4; j++) {
            int cl = wc * 128 + nt * 8 + 2 * q + (j & 1);
            int rn = rowS + 8 * (j >> 1);
            fT[cl * 68 + rn] = acc[nt][j];
        }
    __syncthreads();
    const float* xb = x   + (size_t)b * CC * NN + n0;
    float*       ob = out + (size_t)b * CC * NN + n0;
#pragma unroll
    for (int i = 0; i < 16; i++) {
        int idx = tid + i * 256;
        int cr = idx >> 4;
        int n4 = (idx & 15) * 4;
        float4 t = *(const float4*)&fT[cr * 68 + n4];
        const size_t go = (size_t)cr * NN + n4;
        float4 xv = *(const float4*)(xb + go);
        *(float4*)(ob + go) = make_float4(t.x + xv.x, t.y + xv.y,
                                          t.z + xv.z, t.w + xv.w);
    }
}

// ===========================================================================
extern "C" void kernel_launch(void* const* d_in, const int* in_sizes, int n_in,
                              void* d_out, int out_size) {
    const float* x  = (const float*)d_in[0];
    const float* Wq = (const float*)d_in[1];
    const float* bq = (const float*)d_in[2];
    const float* Wk = (const float*)d_in[3];
    const float* bk = (const float*)d_in[4];
    const float* Wv = (const float*)d_in[5];
    const float* bv = (const float*)d_in[6];
    float* out = (float*)d_out;

    const int pdyn = P_SMEM_FLOATS * 4;   // 130304 B
    cudaFuncSetAttribute(proj_fused_kernel,
                         cudaFuncAttributeMaxDynamicSharedMemorySize, pdyn);
    proj_fused_kernel<<<dim3(NN / 128, BB), 256, pdyn>>>(x, Wq, bq, Wk, bk, Wv, bv);

    const int fdyn = SMEM_FLOATS * 4;     // 100352 B
    cudaFuncSetAttribute(flash_kernel,
                         cudaFuncAttributeMaxDynamicSharedMemorySize, fdyn);
    flash_kernel<<<dim3(NN / 64, BB), 256, fdyn>>>(x, out);
}

// round 16
// speedup vs baseline: 1.0399x; 1.0399x over previous
#include <cuda_runtime.h>
#include <cuda_fp16.h>

#define BB  4
#define CC  256
#define CQK 32
#define NN  4096
#define LOG2E 1.4426950408889634f

// q/k: fp16 [b][n][c], word-pair-permuted per k16 chunk (8 words):
//   stored order [w0,w4,w1,w5,w2,w6,w3,w7] (word = 2 adjacent c).
//   q pre-scaled by log2(e).
// v: fp16 [b][c][m], same word-perm per 8-word (16-m) group.
__device__ __half g_qt[BB * NN * CQK];
__device__ __half g_kt[BB * NN * CQK];
__device__ __half g_v [(size_t)BB * CC * NN];

// ---- flash smem layout (32-bit word slots) — 64-row blocks, 2 sync groups
#define OFF_Q   0            // 64 x 24
#define OFF_KA  1536         // grp A: 2 x 64 x 24
#define OFF_KB  4608         // grp B: 2 x 64 x 24
#define OFF_VA  7680         // grp A: 2 x 128 x 40 (c 0..127)
#define OFF_VB  17920        // grp B: 2 x 128 x 40 (c 128..255)
#define SMEM_FLOATS 28160    // 112640 B; epilogue fT 256x68 reuses OFF_KA..

// ---- proj smem layout (floats)
#define P_OFF_SX 0           // 2 x 128 x 36
#define P_OFF_SW 9216        // 2 x 320 x 36
#define P_OFF_SB 32256       // 320
#define P_SMEM_FLOATS 32576  // 130304 bytes (epilogue 80x132 reuses P_OFF_SW)

// ===========================================================================
__device__ __forceinline__ unsigned smem_u32(const void* p) {
    unsigned a;
    asm("{ .reg .u64 t; cvta.to.shared.u64 t, %1; cvt.u32.u64 %0, t; }"
        : "=r"(a) : "l"(p));
    return a;
}
__device__ __forceinline__ float ex2(float x) {
    float y;
    asm("ex2.approx.ftz.f32 %0, %1;" : "=f"(y) : "f"(x));
    return y;
}
// pack two fp32 -> f16x2 word (lo = first element)
__device__ __forceinline__ unsigned packh(float lo, float hi) {
    unsigned r;
    asm("cvt.rn.f16x2.f32 %0, %1, %2;" : "=r"(r) : "f"(hi), "f"(lo));
    return r;
}
__device__ __forceinline__ void cp16(unsigned dst, const void* src) {
    asm volatile("cp.async.cg.shared.global [%0], [%1], 16;" :: "r"(dst), "l"(src));
}
__device__ __forceinline__ void cp4(unsigned dst, const void* src) {
    asm volatile("cp.async.ca.shared.global [%0], [%1], 4;" :: "r"(dst), "l"(src));
}
#define CP_COMMIT()  asm volatile("cp.async.commit_group;")
#define CP_WAIT(n)   asm volatile("cp.async.wait_group %0;" :: "n"(n))
#define GBAR(id)     asm volatile("bar.sync %0, 128;" :: "r"(id) : "memory")

__device__ __forceinline__ void lds2(unsigned addr, unsigned& x, unsigned& y) {
    asm volatile("ld.shared.v2.b32 {%0, %1}, [%2];" : "=r"(x), "=r"(y) : "r"(addr));
}
__device__ __forceinline__ unsigned lds1(unsigned addr) {
    unsigned v;
    asm volatile("ld.shared.b32 %0, [%1];" : "=r"(v) : "r"(addr));
    return v;
}
__device__ __forceinline__ void mma8(float c[4],
                                     unsigned a0, unsigned a1, unsigned a2, unsigned a3,
                                     unsigned b0, unsigned b1) {
    asm volatile(
        "mma.sync.aligned.m16n8k8.row.col.f32.tf32.tf32.f32 "
        "{%0,%1,%2,%3}, {%4,%5,%6,%7}, {%8,%9}, {%0,%1,%2,%3};"
        : "+f"(c[0]), "+f"(c[1]), "+f"(c[2]), "+f"(c[3])
        : "r"(a0), "r"(a1), "r"(a2), "r"(a3), "r"(b0), "r"(b1));
}
__device__ __forceinline__ void mma16h(float c[4],
                                       unsigned a0, unsigned a1, unsigned a2, unsigned a3,
                                       unsigned b0, unsigned b1) {
    asm volatile(
        "mma.sync.aligned.m16n8k16.row.col.f32.f16.f16.f32 "
        "{%0,%1,%2,%3}, {%4,%5,%6,%7}, {%8,%9}, {%0,%1,%2,%3};"
        : "+f"(c[0]), "+f"(c[1]), "+f"(c[2]), "+f"(c[3])
        : "r"(a0), "r"(a1), "r"(a2), "r"(a3), "r"(b0), "r"(b1));
}

// ===========================================================================
// 1) Fused q+k+v projection via tensor cores (unchanged from R12/R14).
// ===========================================================================
__global__ __launch_bounds__(256, 1) void proj_fused_kernel(
        const float* __restrict__ x,
        const float* __restrict__ Wq, const float* __restrict__ bq,
        const float* __restrict__ Wk, const float* __restrict__ bk,
        const float* __restrict__ Wv, const float* __restrict__ bv) {
    extern __shared__ float psm[];

    const int b   = blockIdx.y;
    const int n0  = blockIdx.x * 128;
    const int tid = threadIdx.x;
    const int wid = tid >> 5, lane = tid & 31;
    const int r4 = lane >> 2, q = lane & 3;
    const int wm = wid >> 1, wn = wid & 1;

    const unsigned sb4 = smem_u32(psm);
    const unsigned sX  = sb4 + P_OFF_SX * 4;
    const unsigned sW  = sb4 + P_OFF_SW * 4;
    float* fB = psm + P_OFF_SB;

    {
        int i = tid;
        if (i < 32) fB[i] = bq[i];
        else if (i < 64) fB[i] = bk[i - 32];
        else fB[i] = bv[i - 64];
        i = tid + 256;
        if (i < 320) fB[i] = bv[i - 64];
    }

    auto issue = [&](int ch) {
        const int buf = ch & 1;
        const unsigned wd = sW + (unsigned)buf * (320 * 36 * 4);
#pragma unroll
        for (int i = 0; i < 10; i++) {
            int idx = tid + i * 256;
            int row = idx >> 3, seg = idx & 7;
            int c = ch * 32 + seg * 4;
            const float* src = (row < 32) ? (Wq + row * 256 + c)
                             : (row < 64) ? (Wk + (row - 32) * 256 + c)
                                          : (Wv + (row - 64) * 256 + c);
            cp16(wd + (unsigned)(row * 36 + seg * 4) * 4, src);
        }
        const unsigned xd = sX + (unsigned)buf * (128 * 36 * 4);
#pragma unroll
        for (int i = 0; i < 16; i++) {
            int idx = tid + i * 256;
            int c = idx >> 7, n = idx & 127;
            cp4(xd + (unsigned)(n * 36 + c) * 4,
                x + ((size_t)b * CC + ch * 32 + c) * NN + n0 + n);
        }
        CP_COMMIT();
    };

    float acc[5][8][4];
#pragma unroll
    for (int mt = 0; mt < 5; mt++)
#pragma unroll
        for (int nt = 0; nt < 8; nt++)
#pragma unroll
            for (int j = 0; j < 4; j++) acc[mt][nt][j] = 0.f;

    issue(0);
    for (int ch = 0; ch < 8; ch++) {
        if (ch < 7) { issue(ch + 1); CP_WAIT(1); }
        else        { CP_WAIT(0); }
        __syncthreads();

        const int buf = ch & 1;
        const unsigned swb = sW + (unsigned)buf * (320 * 36 * 4);
        const unsigned sxb = sX + (unsigned)buf * (128 * 36 * 4);
#pragma unroll
        for (int kk = 0; kk < 4; kk++) {
            unsigned a[5][4];
#pragma unroll
            for (int mt = 0; mt < 5; mt++) {
                unsigned base = swb + (unsigned)((wm * 80 + mt * 16 + r4) * 36 + kk * 8 + q) * 4;
                a[mt][0] = lds1(base);
                a[mt][1] = lds1(base + 8 * 36 * 4);
                a[mt][2] = lds1(base + 16);
                a[mt][3] = lds1(base + 8 * 36 * 4 + 16);
            }
            unsigned bb[8][2];
#pragma unroll
            for (int nt = 0; nt < 8; nt++) {
                unsigned nb = sxb + (unsigned)((wn * 64 + nt * 8 + r4) * 36 + kk * 8 + q) * 4;
                bb[nt][0] = lds1(nb);
                bb[nt][1] = lds1(nb + 16);
            }
#pragma unroll
            for (int mt = 0; mt < 5; mt++)
#pragma unroll
                for (int nt = 0; nt < 8; nt++)
                    mma8(acc[mt][nt], a[mt][0], a[mt][1], a[mt][2], a[mt][3],
                         bb[nt][0], bb[nt][1]);
        }
        __syncthreads();
    }

    float* fE = psm + P_OFF_SW;   // 80 x 132
#pragma unroll 1
    for (int ocg = 0; ocg < 4; ocg++) {
        __syncthreads();
        if (wm == ocg) {
#pragma unroll
            for (int mt = 0; mt < 5; mt++)
#pragma unroll
                for (int nt = 0; nt < 8; nt++)
#pragma unroll
                    for (int j = 0; j < 4; j++) {
                        int row = mt * 16 + r4 + 8 * (j >> 1);
                        int col = wn * 64 + nt * 8 + 2 * q + (j & 1);
                        fE[row * 132 + col] = acc[mt][nt][j] + fB[ocg * 80 + row];
                    }
        }
        __syncthreads();

        if (ocg == 0) {
#pragma unroll
            for (int i = 0; i < 2; i++) {
                int item = tid + i * 256;
                if (item < 256) {
                    int n = item & 127, half = item >> 7;
                    const float sc = half ? 1.0f : LOG2E;
                    float vv[32];
#pragma unroll
                    for (int o = 0; o < 32; o++)
                        vv[o] = fE[(half * 32 + o) * 132 + n] * sc;
                    unsigned w[16];
#pragma unroll
                    for (int j = 0; j < 16; j++) w[j] = packh(vv[2*j], vv[2*j+1]);
                    __half* hdst = (half ? g_kt : g_qt) + ((size_t)b * NN + n0 + n) * CQK;
                    uint4* d = (uint4*)hdst;
                    d[0] = make_uint4(w[0],  w[4],  w[1],  w[5]);
                    d[1] = make_uint4(w[2],  w[6],  w[3],  w[7]);
                    d[2] = make_uint4(w[8],  w[12], w[9],  w[13]);
                    d[3] = make_uint4(w[10], w[14], w[11], w[15]);
                } else {
                    int it = item - 256;
                    if (it < 128) {
                        int row = 64 + (it >> 3), gt = it & 7;
                        int c = row - 64;
                        const float* f = fE + row * 132 + gt * 16;
                        unsigned w[8];
#pragma unroll
                        for (int p = 0; p < 8; p++) w[p] = packh(f[2*p], f[2*p+1]);
                        uint4* d = (uint4*)(g_v + ((size_t)b * CC + c) * NN + n0 + gt * 16);
                        d[0] = make_uint4(w[0], w[4], w[1], w[5]);
                        d[1] = make_uint4(w[2], w[6], w[3], w[7]);
                    }
                }
            }
        } else {
#pragma unroll
            for (int i = 0; i < 3; i++) {
                int item = tid + i * 256;
                if (item < 640) {
                    int row = item >> 3, gt = item & 7;
                    int c = ocg * 80 + row - 64;
                    const float* f = fE + row * 132 + gt * 16;
                    unsigned w[8];
#pragma unroll
                    for (int p = 0; p < 8; p++) w[p] = packh(f[2*p], f[2*p+1]);
                    uint4* d = (uint4*)(g_v + ((size_t)b * CC + c) * NN + n0 + gt * 16);
                    d[0] = make_uint4(w[0], w[4], w[1], w[5]);
                    d[1] = make_uint4(w[2], w[6], w[3], w[7]);
                }
            }
        }
    }
}

// ===========================================================================
// 2) Flash attention, 64-row blocks, 2 CTAs/SM, fp16 k16 mma.
//    TWO INDEPENDENT SYNC GROUPS per CTA: grp = wid>>2 owns a private K copy
//    and private V c-half; syncs via named barrier (1+grp). Groups drift
//    freely -> 4 independent streams per SMSP hide softmax serial chains.
//    Warp tile 16n (wr=wid&3) x 128c (grp half).
// ===========================================================================
__global__ __launch_bounds__(256, 2) void flash_kernel(const float* __restrict__ x,
                                                       float* __restrict__ out) {
    extern __shared__ float sm[];

    const int b   = blockIdx.y;
    const int n0  = blockIdx.x * 64;
    const int tid = threadIdx.x;
    const int wid = tid >> 5, lane = tid & 31;
    const int r4 = lane >> 2, q = lane & 3;
    const int grp = wid >> 2, wr = wid & 3;
    const int gt  = tid & 127;             // thread index within group

    const unsigned sb  = smem_u32(sm);
    const unsigned sQ  = sb + OFF_Q * 4;
    const unsigned sKg = sb + (grp ? OFF_KB : OFF_KA) * 4;
    const unsigned sVg = sb + (grp ? OFF_VB : OFF_VA) * 4;
    const int barid = 1 + grp;

    const __half* qg  = g_qt + ((size_t)b * NN + n0) * CQK;
    const __half* kg0 = g_kt + (size_t)b * NN * CQK;
    const __half* vg0 = g_v  + ((size_t)b * CC + grp * 128) * NN;  // group's c-half

    // ---- prologue: Q (all threads) + group K(0) copy + group V(0) half
    cp16(sQ + (unsigned)((tid >> 2) * 24 + (tid & 3) * 4) * 4,
         qg + (size_t)(tid >> 2) * CQK + (tid & 3) * 8);
#pragma unroll
    for (int i = 0; i < 2; i++) {          // K: 64 rows x 4 cp16
        int item = gt + i * 128;
        int row = item >> 2, seg = item & 3;
        cp16(sKg + (unsigned)(row * 24 + seg * 4) * 4,
             kg0 + (size_t)row * CQK + seg * 8);
    }
#pragma unroll
    for (int i = 0; i < 8; i++) {          // V half: 128 rows x 8 cp16
        int idx = gt + i * 128;
        int row = idx >> 3, p = idx & 7;
        cp16(sVg + (unsigned)(row * 40 + p * 4) * 4,
             vg0 + (size_t)row * NN + p * 8);
    }
    CP_COMMIT();
    CP_WAIT(0);
    __syncthreads();   // Q visible to both groups

    // q fragments: warp owns rows 16*wr..+15 (LOG2E pre-folded)
    const int rowS = 16 * wr + r4;
    unsigned qf[2][4];
#pragma unroll
    for (int kk = 0; kk < 2; kk++) {
        lds2(sQ + (unsigned)(rowS * 24 + kk * 8 + 2 * q) * 4,
             qf[kk][0], qf[kk][2]);
        lds2(sQ + (unsigned)((rowS + 8) * 24 + kk * 8 + 2 * q) * 4,
             qf[kk][1], qf[kk][3]);
    }

    // out accumulator: 16 rows x 128 c -> 16 nt fragments
    float acc[16][4];
#pragma unroll
    for (int nt = 0; nt < 16; nt++)
#pragma unroll
        for (int j = 0; j < 4; j++) acc[nt][j] = 0.f;

    float mA = -1e30f, mB = -1e30f, lA = 0.f, lB = 0.f;

    const int STEPS = NN / 64;
    for (int s = 0; s < STEPS; s++) {
        if (s > 0) { CP_WAIT(1); GBAR(barid); }   // K(s) ready; group done with buf(s^1)

        if (s + 1 < STEPS) {
            const int m1 = (s + 1) * 64;
            // K(s+1): group copy, own commit group
            const unsigned kd = sKg + (unsigned)((s + 1) & 1) * (64 * 24 * 4);
#pragma unroll
            for (int i = 0; i < 2; i++) {
                int item = gt + i * 128;
                int row = item >> 2, seg = item & 3;
                cp16(kd + (unsigned)(row * 24 + seg * 4) * 4,
                     kg0 + (size_t)(m1 + row) * CQK + seg * 8);
            }
            CP_COMMIT();
            // V(s+1) half: separate commit group
            const unsigned vd = sVg + (unsigned)((s + 1) & 1) * (128 * 40 * 4);
#pragma unroll
            for (int i = 0; i < 8; i++) {
                int idx = gt + i * 128;
                int row = idx >> 3, p = idx & 7;
                cp16(vd + (unsigned)(row * 40 + p * 4) * 4,
                     vg0 + (size_t)row * NN + m1 + p * 8);
            }
            CP_COMMIT();
        }

        // ---- scores (fp16 k16): own 16 rows x 64 m (from group K copy)
        const unsigned kbuf = sKg + (unsigned)(s & 1) * (64 * 24 * 4);
        float sacc[8][4];
#pragma unroll
        for (int nt = 0; nt < 8; nt++)
#pragma unroll
            for (int j = 0; j < 4; j++) sacc[nt][j] = 0.f;

#pragma unroll
        for (int kk = 0; kk < 2; kk++) {
#pragma unroll
            for (int nt = 0; nt < 8; nt++) {
                unsigned b0, b1;
                lds2(kbuf + (unsigned)((nt * 8 + r4) * 24 + kk * 8 + 2 * q) * 4,
                     b0, b1);
                mma16h(sacc[nt], qf[kk][0], qf[kk][1], qf[kk][2], qf[kk][3],
                       b0, b1);
            }
        }

        // ---- max reduce (the only full-tile dependency)
        float rmA = sacc[0][0], rmB = sacc[0][2];
#pragma unroll
        for (int nt = 0; nt < 8; nt++) {
            rmA = fmaxf(rmA, fmaxf(sacc[nt][0], sacc[nt][1]));
            rmB = fmaxf(rmB, fmaxf(sacc[nt][2], sacc[nt][3]));
        }
#pragma unroll
        for (int off = 1; off <= 2; off <<= 1) {
            rmA = fmaxf(rmA, __shfl_xor_sync(0xffffffffu, rmA, off));
            rmB = fmaxf(rmB, __shfl_xor_sync(0xffffffffu, rmB, off));
        }
        const float mnA = fmaxf(mA, rmA), mnB = fmaxf(mB, rmB);
        const float scA = ex2(mA - mnA),  scB = ex2(mB - mnB);
        mA = mnA; mB = mnB;

        // ---- rescale acc (warp-local, skip when maxes unchanged)
        if (!__all_sync(0xffffffffu, (scA == 1.f) && (scB == 1.f))) {
#pragma unroll
            for (int nt = 0; nt < 16; nt++) {
                acc[nt][0] *= scA; acc[nt][1] *= scA;
                acc[nt][2] *= scB; acc[nt][3] *= scB;
            }
        }

        // ---- V(s) must be resident before PV reads it
        if (s + 1 < STEPS) { CP_WAIT(2); }   // pending: V(s),K(s+1),V(s+1)
        else               { CP_WAIT(0); }

        // ---- fused softmax + PV: per chunk g {ex2, l-accum, pack, 16 mmas}
        const unsigned vbuf = sVg + (unsigned)(s & 1) * (128 * 40 * 4);
        float lsA = 0.f, lsB = 0.f;
#pragma unroll
        for (int g = 0; g < 4; g++) {
            float p0 = ex2(sacc[2*g][0]   - mnA);
            float p1 = ex2(sacc[2*g][1]   - mnA);
            float p2 = ex2(sacc[2*g][2]   - mnB);
            float p3 = ex2(sacc[2*g][3]   - mnB);
            float p4 = ex2(sacc[2*g+1][0] - mnA);
            float p5 = ex2(sacc[2*g+1][1] - mnA);
            float p6 = ex2(sacc[2*g+1][2] - mnB);
            float p7 = ex2(sacc[2*g+1][3] - mnB);
            lsA += (p0 + p1) + (p4 + p5);
            lsB += (p2 + p3) + (p6 + p7);
            unsigned a0 = packh(p0, p1);
            unsigned a1 = packh(p2, p3);
            unsigned a2 = packh(p4, p5);
            unsigned a3 = packh(p6, p7);
#pragma unroll
            for (int nt = 0; nt < 16; nt++) {
                unsigned b0, b1;
                lds2(vbuf + (unsigned)((nt * 8 + r4) * 40 + g * 8 + 2 * q) * 4,
                     b0, b1);
                mma16h(acc[nt], a0, a1, a2, a3, b0, b1);
            }
        }
#pragma unroll
        for (int off = 1; off <= 2; off <<= 1) {
            lsA += __shfl_xor_sync(0xffffffffu, lsA, off);
            lsB += __shfl_xor_sync(0xffffffffu, lsB, off);
        }
        lA = lA * scA + lsA;
        lB = lB * scB + lsB;
    }

    // ---- normalize by l (warp-local)
    const float linvA = 1.f / lA, linvB = 1.f / lB;
#pragma unroll
    for (int nt = 0; nt < 16; nt++) {
        acc[nt][0] *= linvA; acc[nt][1] *= linvA;
        acc[nt][2] *= linvB; acc[nt][3] *= linvB;
    }

    // ---- epilogue: transpose 64n x 256c -> [c][n] via smem (reuse K+V), +x
    float* fT = sm + OFF_KA;   // 256 x 68
    __syncthreads();           // both groups done with K/V buffers
#pragma unroll
    for (int nt = 0; nt < 16; nt++)
#pragma unroll
        for (int j = 0; j < 4; j++) {
            int cl = grp * 128 + nt * 8 + 2 * q + (j & 1);
            int rn = rowS + 8 * (j >> 1);
            fT[cl * 68 + rn] = acc[nt][j];
        }
    __syncthreads();
    const float* xb = x   + (size_t)b * CC * NN + n0;
    float*       ob = out + (size_t)b * CC * NN + n0;
#pragma unroll
    for (int i = 0; i < 16; i++) {
        int idx = tid + i * 256;
        int cr = idx >> 4;
        int n4 = (idx & 15) * 4;
        float4 t = *(const float4*)&fT[cr * 68 + n4];
        const size_t go = (size_t)cr * NN + n4;
        float4 xv = *(const float4*)(xb + go);
        *(float4*)(ob + go) = make_float4(t.x + xv.x, t.y + xv.y,
                                          t.z + xv.z, t.w + xv.w);
    }
}

// ===========================================================================
extern "C" void kernel_launch(void* const* d_in, const int* in_sizes, int n_in,
                              void* d_out, int out_size) {
    const float* x  = (const float*)d_in[0];
    const float* Wq = (const float*)d_in[1];
    const float* bq = (const float*)d_in[2];
    const float* Wk = (const float*)d_in[3];
    const float* bk = (const float*)d_in[4];
    const float* Wv = (const float*)d_in[5];
    const float* bv = (const float*)d_in[6];
    float* out = (float*)d_out;

    const int pdyn = P_SMEM_FLOATS * 4;   // 130304 B
    cudaFuncSetAttribute(proj_fused_kernel,
                         cudaFuncAttributeMaxDynamicSharedMemorySize, pdyn);
    proj_fused_kernel<<<dim3(NN / 128, BB), 256, pdyn>>>(x, Wq, bq, Wk, bk, Wv, bv);

    const int fdyn = SMEM_FLOATS * 4;     // 112640 B
    cudaFuncSetAttribute(flash_kernel,
                         cudaFuncAttributeMaxDynamicSharedMemorySize, fdyn);
    flash_kernel<<<dim3(NN / 64, BB), 256, fdyn>>>(x, out);
}